// round 17
// baseline (speedup 1.0000x reference)
#include <cuda_runtime.h>

#define T_STEPS 512

// ---- packed f32x2 helpers (sm_100+ PTX) ----
__device__ __forceinline__ unsigned long long pack2(float lo, float hi){
    unsigned long long r;
    asm("mov.b64 %0, {%1, %2};" : "=l"(r) : "f"(lo), "f"(hi));
    return r;
}
__device__ __forceinline__ void ffma2(unsigned long long& acc, unsigned long long a, unsigned long long b){
    asm("fma.rn.f32x2 %0, %1, %2, %0;" : "+l"(acc) : "l"(a), "l"(b));
}
__device__ __forceinline__ float2 unpack2(unsigned long long v){
    float2 f;
    asm("mov.b64 {%0, %1}, %2;" : "=f"(f.x), "=f"(f.y) : "l"(v));
    return f;
}
// HW tanh (MUFU): 1 op, err ~2^-10.8.
__device__ __forceinline__ float tanh_a(float x){
    float r; asm("tanh.approx.f32 %0, %1;" : "=f"(r) : "f"(x)); return r;
}
// sigmoid with the 0.5x PRE-FOLDED into the weights: s = 0.5*tanh(g') + 0.5
__device__ __forceinline__ float sigmoid_pre(float xh){
    return fmaf(0.5f, tanh_a(xh), 0.5f);
}

// Architecture = R7 optimum: TWO batches per warp, one warp per block,
// grid = B/2 = 1024 -> one wave, ~2 warps/SMSP. Fence-free h slab (validated).
// NEW: software-pipelined h round-trip.
//  - batch0's h row lives in persistent regs v0[8]; reloaded RIGHT AFTER its
//    STS, so the 8 LDS.128 issue under batch1's gate chain.
//  - batch1's row v1[8] loads at loop top, and the MAC consumes ALL v0 terms
//    first (64 FFMA2) before the first v1 use -> v1 latency fully covered.
//  => the STS->LDS 29+cyc turnaround leaves the per-step critical path.
__global__ void __launch_bounds__(32, 8) lstm_r17(
    const float* __restrict__ x,
    const float* __restrict__ W_ih,
    const float* __restrict__ W_hh,
    const float* __restrict__ b_ih,
    const float* __restrict__ b_hh,
    const float* __restrict__ W_fc,
    const float* __restrict__ b_fc,
    float* __restrict__ out,
    int B)
{
    const int lane = threadIdx.x;
    const int b0 = blockIdx.x * 2;
    const int b1 = b0 + 1;
    const bool has1 = (b1 < B);
    const int b1m = has1 ? b1 : b0;

    __shared__ __align__(16) float hs[2][32][36];
    __shared__ float wfcs[32];

    // ---- preload shared weights into registers; sigmoid rows pre-scaled ----
    unsigned long long w2[4][16];   // 4 gate rows x 16 packed k-pairs = 128 regs
    unsigned long long wx2[4];
    float bias[4];
#pragma unroll
    for (int r = 0; r < 4; r++){
        const float s = (r == 2) ? 1.0f : 0.5f;   // gate order i,f,g,o
        const int row = r * 32 + lane;
        const float4* wr = reinterpret_cast<const float4*>(W_hh) + row * 8;
#pragma unroll
        for (int q = 0; q < 8; q++){
            float4 v = wr[q];
            w2[r][2*q]   = pack2(s * v.x, s * v.y);
            w2[r][2*q+1] = pack2(s * v.z, s * v.w);
        }
        wx2[r]  = pack2(s * W_ih[row*2 + 0], s * W_ih[row*2 + 1]);
        bias[r] = s * (b_ih[row] + b_hh[row]);
    }
    wfcs[lane] = W_fc[lane];
    const float bfc = b_fc[0];

    float c0 = 0.0f, c1 = 0.0f;
    hs[1][31][lane] = 0.0f;       // h1_{-1} = 0 (read by step 0 from slab)
    __syncwarp();

    // batch0's h_{-1} = 0 lives directly in the pipeline registers
    ulonglong2 v0[8];
#pragma unroll
    for (int q = 0; q < 8; q++){ v0[q].x = 0ull; v0[q].y = 0ull; }

    const float2* xr0 = reinterpret_cast<const float2*>(x) + (size_t)b0  * T_STEPS;
    const float2* xr1 = reinterpret_cast<const float2*>(x) + (size_t)b1m * T_STEPS;

    for (int tb = 0; tb < T_STEPS / 32; tb++){
#pragma unroll 1
        for (int ts = 0; ts < 32; ts++){
            const int t  = (tb << 5) + ts;
            const int rp = (ts + 31) & 31;  // row holding h1_{t-1}

            // batch1's h row: issued now, first consumed ~64 FFMA2 later
            ulonglong2 v1[8];
            const ulonglong2* hp1 = reinterpret_cast<const ulonglong2*>(&hs[1][rp][0]);
#pragma unroll
            for (int q = 0; q < 8; q++) v1[q] = hp1[q];

            // x loads (L1-resident) + acc init: lo = bias + x0*w0, hi = x1*w1
            const float2 xv0 = xr0[t];
            const float2 xv1 = xr1[t];
            unsigned long long xp0 = pack2(xv0.x, xv0.y);
            unsigned long long xp1 = pack2(xv1.x, xv1.y);
            unsigned long long a00 = pack2(bias[0], 0.f), a01 = pack2(bias[1], 0.f);
            unsigned long long a02 = pack2(bias[2], 0.f), a03 = pack2(bias[3], 0.f);
            unsigned long long a10 = a00, a11 = a01, a12 = a02, a13 = a03;
            ffma2(a00, xp0, wx2[0]); ffma2(a01, xp0, wx2[1]);
            ffma2(a02, xp0, wx2[2]); ffma2(a03, xp0, wx2[3]);
            ffma2(a10, xp1, wx2[0]); ffma2(a11, xp1, wx2[1]);
            ffma2(a12, xp1, wx2[2]); ffma2(a13, xp1, wx2[3]);

            // ---- MAC half A: batch 0 from pipeline regs (ready now) ----
#pragma unroll
            for (int q = 0; q < 8; q++){
                ffma2(a00, v0[q].x, w2[0][2*q]);   ffma2(a01, v0[q].x, w2[1][2*q]);
                ffma2(a02, v0[q].x, w2[2][2*q]);   ffma2(a03, v0[q].x, w2[3][2*q]);
                ffma2(a00, v0[q].y, w2[0][2*q+1]); ffma2(a01, v0[q].y, w2[1][2*q+1]);
                ffma2(a02, v0[q].y, w2[2][2*q+1]); ffma2(a03, v0[q].y, w2[3][2*q+1]);
            }
            // ---- MAC half B: batch 1 (v1 loads have landed by now) ----
#pragma unroll
            for (int q = 0; q < 8; q++){
                ffma2(a10, v1[q].x, w2[0][2*q]);   ffma2(a11, v1[q].x, w2[1][2*q]);
                ffma2(a12, v1[q].x, w2[2][2*q]);   ffma2(a13, v1[q].x, w2[3][2*q]);
                ffma2(a10, v1[q].y, w2[0][2*q+1]); ffma2(a11, v1[q].y, w2[1][2*q+1]);
                ffma2(a12, v1[q].y, w2[2][2*q+1]); ffma2(a13, v1[q].y, w2[3][2*q+1]);
            }

            // gates, batch 0; then STS + immediate pipeline reload of v0,
            // whose LDS latency hides under batch 1's gate chain below
            {
                float2 f0 = unpack2(a00), f1 = unpack2(a01);
                float2 f2 = unpack2(a02), f3 = unpack2(a03);
                const float ig = sigmoid_pre(f0.x + f0.y);
                const float fg = sigmoid_pre(f1.x + f1.y);
                const float gg = tanh_a    (f2.x + f2.y);
                const float og = sigmoid_pre(f3.x + f3.y);
                c0 = fmaf(fg, c0, ig * gg);
                hs[0][ts][lane] = og * tanh_a(c0);
            }
            {
                const ulonglong2* hp0n = reinterpret_cast<const ulonglong2*>(&hs[0][ts][0]);
#pragma unroll
                for (int q = 0; q < 8; q++) v0[q] = hp0n[q];   // same-warp in-order LSU
            }

            // gates, batch 1
            {
                float2 f0 = unpack2(a10), f1 = unpack2(a11);
                float2 f2 = unpack2(a12), f3 = unpack2(a13);
                const float ig = sigmoid_pre(f0.x + f0.y);
                const float fg = sigmoid_pre(f1.x + f1.y);
                const float gg = tanh_a    (f2.x + f2.y);
                const float og = sigmoid_pre(f3.x + f3.y);
                c1 = fmaf(fg, c1, ig * gg);
                hs[1][ts][lane] = og * tanh_a(c1);
            }
            // no fence: next iteration's v1 LDS is ordered after this STS by
            // the per-warp in-order LSU (validated in R15/R16)
        }

        // ---- deferred FC head for this 32-step chunk ----
        __syncwarp();
        float p0 = 0.0f, p1 = 0.0f;
#pragma unroll
        for (int k = 0; k < 32; k++){
            const float w = wfcs[k];
            p0 = fmaf(hs[0][lane][k], w, p0);
            p1 = fmaf(hs[1][lane][k], w, p1);
        }
        const int to = (tb << 5) + lane;
        out[(size_t)b0 * T_STEPS + to] = p0 + bfc;
        if (has1) out[(size_t)b1 * T_STEPS + to] = p1 + bfc;
        __syncwarp();   // chunk rows may be overwritten next chunk
    }
}

extern "C" void kernel_launch(void* const* d_in, const int* in_sizes, int n_in,
                              void* d_out, int out_size)
{
    const float* x   = (const float*)d_in[0];
    const float* Wih = (const float*)d_in[1];
    const float* Whh = (const float*)d_in[2];
    const float* bih = (const float*)d_in[3];
    const float* bhh = (const float*)d_in[4];
    const float* Wfc = (const float*)d_in[5];
    const float* bfc = (const float*)d_in[6];
    float* out = (float*)d_out;

    const int B = out_size / T_STEPS;      // OUT=1 -> out_size = B*T
    const int grid = (B + 1) / 2;          // two batch elements per warp
    lstm_r17<<<grid, 32>>>(x, Wih, Whh, bih, bhh, Wfc, bfc, out, B);
}